// round 6
// baseline (speedup 1.0000x reference)
#include <cuda_runtime.h>
#include <cuda_bf16.h>

// GCN 3-layer, N=100000, E=800000. Aggregate in the smaller dim per layer.
// Self-loop (norm = 1/deg) folded into per-node combine steps.
// R5: packed fma.rn.f32x2 in the 128x64 GEMM; 4-thread/edge layer-2 scatter.

static constexpr int N = 100000;
static constexpr int E = 800000;

__device__ float4 g_agg1[N];        // [N,4]
__device__ float4 g_t2[N * 16];     // [N,64]  (x@W1->relu)@W2
__device__ float4 g_agg2[N * 16];   // [N,64]
__device__ float  g_t3[N];
__device__ float  g_deg[N];
__device__ float  g_dis[N];         // rsqrt(deg)
__device__ float  g_dis2[N];        // 1/deg
__device__ int    g_src[E];
__device__ int    g_dst[E];
__device__ float  g_norm[E];
__device__ int    g_is64;

__device__ __forceinline__ void red_add_v4(float* p, float4 v) {
    asm volatile("red.global.add.v4.f32 [%0], {%1,%2,%3,%4};"
                 :: "l"(p), "f"(v.x), "f"(v.y), "f"(v.z), "f"(v.w)
                 : "memory");
}
__device__ __forceinline__ unsigned long long pack2(float v) {
    unsigned long long r;
    asm("mov.b64 %0, {%1, %1};" : "=l"(r) : "f"(v));
    return r;
}
__device__ __forceinline__ float2 unpk2(unsigned long long v) {
    float2 f;
    asm("mov.b64 {%0, %1}, %2;" : "=f"(f.x), "=f"(f.y) : "l"(v));
    return f;
}
__device__ __forceinline__ unsigned long long fma2(
    unsigned long long a, unsigned long long b, unsigned long long c) {
    unsigned long long d;
    asm("fma.rn.f32x2 %0, %1, %2, %3;" : "=l"(d) : "l"(a), "l"(b), "l"(c));
    return d;
}

// ---------------- kernels ----------------

__global__ void k_init() {
    int i = blockIdx.x * blockDim.x + threadIdx.x;
    int stride = gridDim.x * blockDim.x;
    const float4 z4 = make_float4(0.f, 0.f, 0.f, 0.f);
    for (int j = i; j < N; j += stride) {
        g_deg[j] = 1.0f;            // self-loop weight
        g_agg1[j] = z4;
    }
    for (int j = i; j < N * 16; j += stride) g_agg2[j] = z4;
}

// dtype sniff: int64 values < 2^31 -> all odd int32 words zero.
__global__ void k_detect(const int* __restrict__ ei32) {
    __shared__ unsigned s[256];
    unsigned acc = 0;
    for (int i = threadIdx.x; i < 8192; i += 256) acc |= (unsigned)ei32[2 * i + 1];
    s[threadIdx.x] = acc;
    __syncthreads();
    for (int o = 128; o; o >>= 1) {
        if (threadIdx.x < o) s[threadIdx.x] |= s[threadIdx.x + o];
        __syncthreads();
    }
    if (threadIdx.x == 0) g_is64 = (s[0] == 0) ? 1 : 0;
}

// decode indices (either dtype) + weighted in-degree
__global__ void k_decode_deg(const int* __restrict__ ei32, const float* __restrict__ w) {
    int e = blockIdx.x * blockDim.x + threadIdx.x;
    if (e >= E) return;
    int s, d;
    if (g_is64) { s = ei32[2 * e]; d = ei32[2 * (E + e)]; }
    else        { s = ei32[e];     d = ei32[E + e]; }
    if ((unsigned)s >= (unsigned)N) s = 0;
    if ((unsigned)d >= (unsigned)N) d = 0;
    g_src[e] = s;
    g_dst[e] = d;
    atomicAdd(&g_deg[d], w[e]);
}

__global__ void k_dis() {
    int i = blockIdx.x * blockDim.x + threadIdx.x;
    if (i >= N) return;
    float dg = g_deg[i];
    g_dis[i]  = rsqrtf(dg);
    g_dis2[i] = 1.0f / dg;
}

// per-edge norm + layer-1 aggregation (dim 4)
__global__ void k_norm_agg1(const float* __restrict__ x, const float* __restrict__ w) {
    int e = blockIdx.x * blockDim.x + threadIdx.x;
    if (e >= E) return;
    int s = g_src[e], d = g_dst[e];
    float nr = g_dis[s] * w[e] * g_dis[d];
    g_norm[e] = nr;
    float4 v = ((const float4*)x)[s];
    v.x *= nr; v.y *= nr; v.z *= nr; v.w *= nr;
    red_add_v4((float*)&g_agg1[d], v);
}

// fused: h1_row = relu(v @ W1 + b1) streamed through registers; t2 = h1_row @ W2
// inner loop uses packed fma.rn.f32x2 (2 fp32 FMA per fma-pipe issue)
__global__ __launch_bounds__(128) void k_l1gemm2(
    const float* __restrict__ x, const float* __restrict__ W1,
    const float* __restrict__ b1, const float* __restrict__ W2) {
    __shared__ float sW2[128 * 64];   // 32KB
    __shared__ float sW1[4 * 128];    // 2KB
    __shared__ float sb1[128];
    for (int t = threadIdx.x; t < 128 * 64; t += 128) sW2[t] = W2[t];
    for (int t = threadIdx.x; t < 4 * 128; t += 128)  sW1[t] = W1[t];
    if (threadIdx.x < 128) sb1[threadIdx.x] = b1[threadIdx.x];
    __syncthreads();

    int node = blockIdx.x * blockDim.x + threadIdx.x;
    if (node >= N) return;

    float4 ag = g_agg1[node];
    float4 xv = ((const float4*)x)[node];
    float s2 = g_dis2[node];
    float v0 = ag.x + s2 * xv.x;
    float v1 = ag.y + s2 * xv.y;
    float v2 = ag.z + s2 * xv.z;
    float v3 = ag.w + s2 * xv.w;

    unsigned long long acc[32];
#pragma unroll
    for (int c = 0; c < 32; c++) acc[c] = 0ULL;

#pragma unroll 1
    for (int k4 = 0; k4 < 32; k4++) {
        // h1[k4*4 .. k4*4+3] on the fly
        float4 r0 = ((const float4*)sW1)[k4];
        float4 r1 = ((const float4*)(sW1 + 128))[k4];
        float4 r2 = ((const float4*)(sW1 + 256))[k4];
        float4 r3 = ((const float4*)(sW1 + 384))[k4];
        float4 bb = ((const float4*)sb1)[k4];
        unsigned long long ax = pack2(fmaxf(bb.x + v0 * r0.x + v1 * r1.x + v2 * r2.x + v3 * r3.x, 0.f));
        unsigned long long ay = pack2(fmaxf(bb.y + v0 * r0.y + v1 * r1.y + v2 * r2.y + v3 * r3.y, 0.f));
        unsigned long long az = pack2(fmaxf(bb.z + v0 * r0.z + v1 * r1.z + v2 * r2.z + v3 * r3.z, 0.f));
        unsigned long long aw = pack2(fmaxf(bb.w + v0 * r0.w + v1 * r1.w + v2 * r2.w + v3 * r3.w, 0.f));

        const unsigned long long* w2 = (const unsigned long long*)&sW2[k4 * 4 * 64];
#pragma unroll
        for (int c = 0; c < 32; c++) {
            unsigned long long a = fma2(ax, w2[c], acc[c]);
            a = fma2(ay, w2[32 + c], a);
            a = fma2(az, w2[64 + c], a);
            acc[c] = fma2(aw, w2[96 + c], a);
        }
    }
    float4* out = &g_t2[node * 16];
#pragma unroll
    for (int c4 = 0; c4 < 16; c4++) {
        float2 lo = unpk2(acc[2 * c4]);
        float2 hi = unpk2(acc[2 * c4 + 1]);
        out[c4] = make_float4(lo.x, lo.y, hi.x, hi.y);
    }
}

// layer-2 aggregation in dim 64: 4 threads/edge, 4 float4 chunks each
__global__ void k_agg2() {
    int idx = blockIdx.x * blockDim.x + threadIdx.x;
    if (idx >= E * 4) return;
    int e = idx >> 2, q = idx & 3;
    int s = g_src[e], d = g_dst[e];
    float nr = g_norm[e];
    const float4* tp = &g_t2[s * 16];
    float4* ap = (float4*)&g_agg2[d * 16];
    float4 v0 = tp[q],      v1 = tp[4 + q], v2 = tp[8 + q], v3 = tp[12 + q];
    v0.x *= nr; v0.y *= nr; v0.z *= nr; v0.w *= nr;
    v1.x *= nr; v1.y *= nr; v1.z *= nr; v1.w *= nr;
    v2.x *= nr; v2.y *= nr; v2.z *= nr; v2.w *= nr;
    v3.x *= nr; v3.y *= nr; v3.z *= nr; v3.w *= nr;
    red_add_v4((float*)&ap[q],      v0);
    red_add_v4((float*)&ap[4 + q],  v1);
    red_add_v4((float*)&ap[8 + q],  v2);
    red_add_v4((float*)&ap[12 + q], v3);
}

// fused: h2 = relu(agg2 + dis2*t2 + b2); t3 = h2 . W3; out = dis2*t3 + b3
__global__ void k_l2gemm3(const float* __restrict__ b2, const float* __restrict__ W3,
                          const float* __restrict__ b3, float* __restrict__ out) {
    __shared__ float sw[64];
    __shared__ float sb2[64];
    if (threadIdx.x < 64) { sw[threadIdx.x] = W3[threadIdx.x]; sb2[threadIdx.x] = b2[threadIdx.x]; }
    __syncthreads();
    int gw = (blockIdx.x * blockDim.x + threadIdx.x) >> 5;
    int lane = threadIdx.x & 31;
    if (gw >= N) return;
    float s2 = g_dis2[gw];
    float2 a = ((const float2*)((const float*)g_agg2 + gw * 64))[lane];
    float2 t = ((const float2*)((const float*)g_t2   + gw * 64))[lane];
    float h0 = fmaxf(a.x + s2 * t.x + sb2[2 * lane],     0.f);
    float h1 = fmaxf(a.y + s2 * t.y + sb2[2 * lane + 1], 0.f);
    float p = h0 * sw[2 * lane] + h1 * sw[2 * lane + 1];
#pragma unroll
    for (int off = 16; off; off >>= 1) p += __shfl_down_sync(0xffffffffu, p, off);
    if (lane == 0) {
        g_t3[gw] = p;
        out[gw] = s2 * p + b3[0];   // self-loop + bias; edge atomics add on top
    }
}

// layer-3 aggregation (scalar atomics into out)
__global__ void k_agg3(float* __restrict__ out) {
    int e = blockIdx.x * blockDim.x + threadIdx.x;
    if (e >= E) return;
    atomicAdd(&out[g_dst[e]], g_norm[e] * g_t3[g_src[e]]);
}

// ---------------- launch ----------------
extern "C" void kernel_launch(void* const* d_in, const int* in_sizes, int n_in,
                              void* d_out, int out_size) {
    const float* x  = (const float*)d_in[0];
    const int*   ei = (const int*)d_in[1];      // dtype sniffed on device
    const float* w  = (const float*)d_in[2];
    const float* W1 = (const float*)d_in[3];
    const float* b1 = (const float*)d_in[4];
    const float* W2 = (const float*)d_in[5];
    const float* b2 = (const float*)d_in[6];
    const float* W3 = (const float*)d_in[7];
    const float* b3 = (const float*)d_in[8];
    float* out = (float*)d_out;

    const int B = 256;

    k_init<<<2048, B>>>();
    k_detect<<<1, 256>>>(ei);
    k_decode_deg<<<(E + B - 1) / B, B>>>(ei, w);
    k_dis<<<(N + B - 1) / B, B>>>();
    k_norm_agg1<<<(E + B - 1) / B, B>>>(x, w);
    k_l1gemm2<<<(N + 127) / 128, 128>>>(x, W1, b1, W2);
    k_agg2<<<(E * 4 + B - 1) / B, B>>>();
    k_l2gemm3<<<(N * 32 + B - 1) / B, B>>>(b2, W3, b3, out);
    k_agg3<<<(E + B - 1) / B, B>>>(out);
}

// round 7
// speedup vs baseline: 1.0094x; 1.0094x over previous
#include <cuda_runtime.h>
#include <cuda_bf16.h>

// GCN 3-layer, N=100000, E=800000. Aggregate in the smaller dim per layer.
// Self-loop (norm = 1/deg) folded into per-node combine steps.
// R6: R4 hot-kernel forms (measured best) + k_init/k_dis eliminated:
//   - deg/agg1 init folded into grid-wide detect kernel
//   - agg2 zeroing folded into the GEMM kernel (hidden behind FFMA)
//   - rsqrt/rcp of deg computed on the fly where needed

static constexpr int N = 100000;
static constexpr int E = 800000;

__device__ float4 g_agg1[N];        // [N,4]
__device__ float4 g_t2[N * 16];     // [N,64]  (x@W1->relu)@W2
__device__ float4 g_agg2[N * 16];   // [N,64]
__device__ float  g_t3[N];
__device__ float  g_deg[N];
__device__ float  g_norm[E];
__device__ int    g_src[E];
__device__ int    g_dst[E];
__device__ int    g_is64;

__device__ __forceinline__ void red_add_v4(float* p, float4 v) {
    asm volatile("red.global.add.v4.f32 [%0], {%1,%2,%3,%4};"
                 :: "l"(p), "f"(v.x), "f"(v.y), "f"(v.z), "f"(v.w)
                 : "memory");
}

// ---------------- kernels ----------------

// grid-wide: init deg=1 (self-loop) and agg1=0; block 0 sniffs edge dtype.
// int64 values < 2^31 -> every odd int32 word is zero.
__global__ void k_detect_init(const int* __restrict__ ei32) {
    int i = blockIdx.x * blockDim.x + threadIdx.x;
    int stride = gridDim.x * blockDim.x;
    const float4 z4 = make_float4(0.f, 0.f, 0.f, 0.f);
    for (int j = i; j < N; j += stride) {
        g_deg[j] = 1.0f;
        g_agg1[j] = z4;
    }
    if (blockIdx.x == 0) {
        __shared__ unsigned s[256];
        unsigned acc = 0;
        for (int t = threadIdx.x; t < 8192; t += 256) acc |= (unsigned)ei32[2 * t + 1];
        s[threadIdx.x] = acc;
        __syncthreads();
        for (int o = 128; o; o >>= 1) {
            if (threadIdx.x < o) s[threadIdx.x] |= s[threadIdx.x + o];
            __syncthreads();
        }
        if (threadIdx.x == 0) g_is64 = (s[0] == 0) ? 1 : 0;
    }
}

// decode indices (either dtype) + weighted in-degree
__global__ void k_decode_deg(const int* __restrict__ ei32, const float* __restrict__ w) {
    int e = blockIdx.x * blockDim.x + threadIdx.x;
    if (e >= E) return;
    int s, d;
    if (g_is64) { s = ei32[2 * e]; d = ei32[2 * (E + e)]; }
    else        { s = ei32[e];     d = ei32[E + e]; }
    if ((unsigned)s >= (unsigned)N) s = 0;
    if ((unsigned)d >= (unsigned)N) d = 0;
    g_src[e] = s;
    g_dst[e] = d;
    atomicAdd(&g_deg[d], w[e]);
}

// per-edge norm (rsqrt on the fly) + layer-1 aggregation (dim 4)
__global__ void k_norm_agg1(const float* __restrict__ x, const float* __restrict__ w) {
    int e = blockIdx.x * blockDim.x + threadIdx.x;
    if (e >= E) return;
    int s = g_src[e], d = g_dst[e];
    float nr = rsqrtf(g_deg[s]) * w[e] * rsqrtf(g_deg[d]);
    g_norm[e] = nr;
    float4 v = ((const float4*)x)[s];
    v.x *= nr; v.y *= nr; v.z *= nr; v.w *= nr;
    red_add_v4((float*)&g_agg1[d], v);
}

// fused: h1_row = relu(v @ W1 + b1) streamed through registers; t2 = h1_row @ W2.
// Also zeroes this node's g_agg2 row (hidden behind the FFMA-bound mainloop).
__global__ __launch_bounds__(128) void k_l1gemm2(
    const float* __restrict__ x, const float* __restrict__ W1,
    const float* __restrict__ b1, const float* __restrict__ W2) {
    __shared__ float sW2[128 * 64];   // 32KB
    __shared__ float sW1[4 * 128];    // 2KB
    __shared__ float sb1[128];
    for (int t = threadIdx.x; t < 128 * 64; t += 128) sW2[t] = W2[t];
    for (int t = threadIdx.x; t < 4 * 128; t += 128)  sW1[t] = W1[t];
    if (threadIdx.x < 128) sb1[threadIdx.x] = b1[threadIdx.x];
    __syncthreads();

    int node = blockIdx.x * blockDim.x + threadIdx.x;
    if (node >= N) return;

    // zero this node's agg2 row (replaces the dedicated init kernel)
    {
        const float4 z4 = make_float4(0.f, 0.f, 0.f, 0.f);
        float4* a2 = &g_agg2[node * 16];
#pragma unroll
        for (int c = 0; c < 16; c++) a2[c] = z4;
    }

    float4 ag = g_agg1[node];
    float4 xv = ((const float4*)x)[node];
    float s2 = 1.0f / g_deg[node];
    float v0 = ag.x + s2 * xv.x;
    float v1 = ag.y + s2 * xv.y;
    float v2 = ag.z + s2 * xv.z;
    float v3 = ag.w + s2 * xv.w;

    float acc[64];
#pragma unroll
    for (int c = 0; c < 64; c++) acc[c] = 0.0f;

#pragma unroll 1
    for (int k4 = 0; k4 < 32; k4++) {
        float4 r0 = ((const float4*)sW1)[k4];
        float4 r1 = ((const float4*)(sW1 + 128))[k4];
        float4 r2 = ((const float4*)(sW1 + 256))[k4];
        float4 r3 = ((const float4*)(sW1 + 384))[k4];
        float4 bb = ((const float4*)sb1)[k4];
        float4 a;
        a.x = fmaxf(bb.x + v0 * r0.x + v1 * r1.x + v2 * r2.x + v3 * r3.x, 0.f);
        a.y = fmaxf(bb.y + v0 * r0.y + v1 * r1.y + v2 * r2.y + v3 * r3.y, 0.f);
        a.z = fmaxf(bb.z + v0 * r0.z + v1 * r1.z + v2 * r2.z + v3 * r3.z, 0.f);
        a.w = fmaxf(bb.w + v0 * r0.w + v1 * r1.w + v2 * r2.w + v3 * r3.w, 0.f);

        const float* w = &sW2[k4 * 4 * 64];
#pragma unroll
        for (int c = 0; c < 64; c++) {
            acc[c] += a.x * w[c];
            acc[c] += a.y * w[64 + c];
            acc[c] += a.z * w[128 + c];
            acc[c] += a.w * w[192 + c];
        }
    }
    float4* out = &g_t2[node * 16];
#pragma unroll
    for (int c4 = 0; c4 < 16; c4++)
        out[c4] = make_float4(acc[4 * c4], acc[4 * c4 + 1], acc[4 * c4 + 2], acc[4 * c4 + 3]);
}

// layer-2 aggregation in dim 64: 16 threads (float4 chunks) per edge
__global__ void k_agg2() {
    int idx = blockIdx.x * blockDim.x + threadIdx.x;
    if (idx >= E * 16) return;
    int e = idx >> 4, c = idx & 15;
    int s = g_src[e], d = g_dst[e];
    float nr = g_norm[e];
    float4 v = g_t2[s * 16 + c];
    v.x *= nr; v.y *= nr; v.z *= nr; v.w *= nr;
    red_add_v4((float*)&g_agg2[d * 16 + c], v);
}

// fused: h2 = relu(agg2 + dis2*t2 + b2); t3 = h2 . W3; out = dis2*t3 + b3
__global__ void k_l2gemm3(const float* __restrict__ b2, const float* __restrict__ W3,
                          const float* __restrict__ b3, float* __restrict__ out) {
    __shared__ float sw[64];
    __shared__ float sb2[64];
    if (threadIdx.x < 64) { sw[threadIdx.x] = W3[threadIdx.x]; sb2[threadIdx.x] = b2[threadIdx.x]; }
    __syncthreads();
    int gw = (blockIdx.x * blockDim.x + threadIdx.x) >> 5;
    int lane = threadIdx.x & 31;
    if (gw >= N) return;
    float s2 = 1.0f / g_deg[gw];
    float2 a = ((const float2*)((const float*)g_agg2 + gw * 64))[lane];
    float2 t = ((const float2*)((const float*)g_t2   + gw * 64))[lane];
    float h0 = fmaxf(a.x + s2 * t.x + sb2[2 * lane],     0.f);
    float h1 = fmaxf(a.y + s2 * t.y + sb2[2 * lane + 1], 0.f);
    float p = h0 * sw[2 * lane] + h1 * sw[2 * lane + 1];
#pragma unroll
    for (int off = 16; off; off >>= 1) p += __shfl_down_sync(0xffffffffu, p, off);
    if (lane == 0) {
        g_t3[gw] = p;
        out[gw] = s2 * p + b3[0];   // self-loop + bias; edge atomics add on top
    }
}

// layer-3 aggregation (scalar atomics into out)
__global__ void k_agg3(float* __restrict__ out) {
    int e = blockIdx.x * blockDim.x + threadIdx.x;
    if (e >= E) return;
    atomicAdd(&out[g_dst[e]], g_norm[e] * g_t3[g_src[e]]);
}

// ---------------- launch ----------------
extern "C" void kernel_launch(void* const* d_in, const int* in_sizes, int n_in,
                              void* d_out, int out_size) {
    const float* x  = (const float*)d_in[0];
    const int*   ei = (const int*)d_in[1];      // dtype sniffed on device
    const float* w  = (const float*)d_in[2];
    const float* W1 = (const float*)d_in[3];
    const float* b1 = (const float*)d_in[4];
    const float* W2 = (const float*)d_in[5];
    const float* b2 = (const float*)d_in[6];
    const float* W3 = (const float*)d_in[7];
    const float* b3 = (const float*)d_in[8];
    float* out = (float*)d_out;

    const int B = 256;

    k_detect_init<<<(N + B - 1) / B, B>>>(ei);
    k_decode_deg<<<(E + B - 1) / B, B>>>(ei, w);
    k_norm_agg1<<<(E + B - 1) / B, B>>>(x, w);
    k_l1gemm2<<<(N + 127) / 128, 128>>>(x, W1, b1, W2);
    k_agg2<<<(E * 16 + B - 1) / B, B>>>();
    k_l2gemm3<<<(N * 32 + B - 1) / B, B>>>(b2, W3, b3, out);
    k_agg3<<<(E + B - 1) / B, B>>>(out);
}

// round 8
// speedup vs baseline: 1.0363x; 1.0267x over previous
#include <cuda_runtime.h>
#include <cuda_bf16.h>

// GCN 3-layer, N=100000, E=800000. Aggregate in the smaller dim per layer.
// Self-loop (norm = 1/deg) folded into per-node combine steps.
// R7: k_l1gemm2 was measured LDS-bandwidth-bound (L1=66%, fma=26%).
//     M-block the GEMM: 2 nodes per thread -> each shared W2 read feeds 2 nodes,
//     halving LDS bytes/FMA (4 -> 2). LDS floor ~42us == FMA floor ~43us.

static constexpr int N = 100000;
static constexpr int E = 800000;

__device__ float4 g_agg1[N];        // [N,4]
__device__ float4 g_t2[N * 16];     // [N,64]  (x@W1->relu)@W2
__device__ float4 g_agg2[N * 16];   // [N,64]
__device__ float  g_t3[N];
__device__ float  g_deg[N];
__device__ float  g_norm[E];
__device__ int    g_src[E];
__device__ int    g_dst[E];
__device__ int    g_is64;

__device__ __forceinline__ void red_add_v4(float* p, float4 v) {
    asm volatile("red.global.add.v4.f32 [%0], {%1,%2,%3,%4};"
                 :: "l"(p), "f"(v.x), "f"(v.y), "f"(v.z), "f"(v.w)
                 : "memory");
}

// ---------------- kernels ----------------

// grid-wide: init deg=1 (self-loop) and agg1=0; block 0 sniffs edge dtype.
__global__ void k_detect_init(const int* __restrict__ ei32) {
    int i = blockIdx.x * blockDim.x + threadIdx.x;
    int stride = gridDim.x * blockDim.x;
    const float4 z4 = make_float4(0.f, 0.f, 0.f, 0.f);
    for (int j = i; j < N; j += stride) {
        g_deg[j] = 1.0f;
        g_agg1[j] = z4;
    }
    if (blockIdx.x == 0) {
        __shared__ unsigned s[256];
        unsigned acc = 0;
        for (int t = threadIdx.x; t < 8192; t += 256) acc |= (unsigned)ei32[2 * t + 1];
        s[threadIdx.x] = acc;
        __syncthreads();
        for (int o = 128; o; o >>= 1) {
            if (threadIdx.x < o) s[threadIdx.x] |= s[threadIdx.x + o];
            __syncthreads();
        }
        if (threadIdx.x == 0) g_is64 = (s[0] == 0) ? 1 : 0;
    }
}

// decode indices (either dtype) + weighted in-degree
__global__ void k_decode_deg(const int* __restrict__ ei32, const float* __restrict__ w) {
    int e = blockIdx.x * blockDim.x + threadIdx.x;
    if (e >= E) return;
    int s, d;
    if (g_is64) { s = ei32[2 * e]; d = ei32[2 * (E + e)]; }
    else        { s = ei32[e];     d = ei32[E + e]; }
    if ((unsigned)s >= (unsigned)N) s = 0;
    if ((unsigned)d >= (unsigned)N) d = 0;
    g_src[e] = s;
    g_dst[e] = d;
    atomicAdd(&g_deg[d], w[e]);
}

// per-edge norm (rsqrt on the fly) + layer-1 aggregation (dim 4)
__global__ void k_norm_agg1(const float* __restrict__ x, const float* __restrict__ w) {
    int e = blockIdx.x * blockDim.x + threadIdx.x;
    if (e >= E) return;
    int s = g_src[e], d = g_dst[e];
    float nr = rsqrtf(g_deg[s]) * w[e] * rsqrtf(g_deg[d]);
    g_norm[e] = nr;
    float4 v = ((const float4*)x)[s];
    v.x *= nr; v.y *= nr; v.z *= nr; v.w *= nr;
    red_add_v4((float*)&g_agg1[d], v);
}

// fused l1+gemm2, 2 nodes per thread (shared W2 reads amortized 2x).
// h1 rows computed on the fly; also zeroes the nodes' g_agg2 rows.
__global__ __launch_bounds__(128) void k_l1gemm2(
    const float* __restrict__ x, const float* __restrict__ W1,
    const float* __restrict__ b1, const float* __restrict__ W2) {
    __shared__ float sW2[128 * 64];   // 32KB
    __shared__ float sW1[4 * 128];    // 2KB
    __shared__ float sb1[128];
    for (int t = threadIdx.x; t < 128 * 64; t += 128) sW2[t] = W2[t];
    for (int t = threadIdx.x; t < 4 * 128; t += 128)  sW1[t] = W1[t];
    if (threadIdx.x < 128) sb1[threadIdx.x] = b1[threadIdx.x];
    __syncthreads();

    int n0 = blockIdx.x * 256 + threadIdx.x;   // node A
    int n1 = n0 + 128;                         // node B
    bool p0 = n0 < N, p1 = n1 < N;
    if (!p0) return;                           // (n1<n0 impossible)

    const float4 z4 = make_float4(0.f, 0.f, 0.f, 0.f);
    // zero agg2 rows (replaces dedicated init kernel)
    {
        float4* a2 = &g_agg2[n0 * 16];
#pragma unroll
        for (int c = 0; c < 16; c++) a2[c] = z4;
        if (p1) {
            float4* b2z = &g_agg2[n1 * 16];
#pragma unroll
            for (int c = 0; c < 16; c++) b2z[c] = z4;
        }
    }

    float u0, u1, u2, u3;   // node A input vec
    float w0, w1, w2, w3;   // node B input vec
    {
        float4 ag = g_agg1[n0];
        float4 xv = ((const float4*)x)[n0];
        float s2 = 1.0f / g_deg[n0];
        u0 = ag.x + s2 * xv.x; u1 = ag.y + s2 * xv.y;
        u2 = ag.z + s2 * xv.z; u3 = ag.w + s2 * xv.w;
    }
    if (p1) {
        float4 ag = g_agg1[n1];
        float4 xv = ((const float4*)x)[n1];
        float s2 = 1.0f / g_deg[n1];
        w0 = ag.x + s2 * xv.x; w1 = ag.y + s2 * xv.y;
        w2 = ag.z + s2 * xv.z; w3 = ag.w + s2 * xv.w;
    } else {
        w0 = w1 = w2 = w3 = 0.f;
    }

    float acc0[64], acc1[64];
#pragma unroll
    for (int c = 0; c < 64; c++) { acc0[c] = 0.f; acc1[c] = 0.f; }

#pragma unroll 1
    for (int k4 = 0; k4 < 32; k4++) {
        float4 r0 = ((const float4*)sW1)[k4];
        float4 r1 = ((const float4*)(sW1 + 128))[k4];
        float4 r2 = ((const float4*)(sW1 + 256))[k4];
        float4 r3 = ((const float4*)(sW1 + 384))[k4];
        float4 bb = ((const float4*)sb1)[k4];
        float4 a, b;
        a.x = fmaxf(bb.x + u0 * r0.x + u1 * r1.x + u2 * r2.x + u3 * r3.x, 0.f);
        a.y = fmaxf(bb.y + u0 * r0.y + u1 * r1.y + u2 * r2.y + u3 * r3.y, 0.f);
        a.z = fmaxf(bb.z + u0 * r0.z + u1 * r1.z + u2 * r2.z + u3 * r3.z, 0.f);
        a.w = fmaxf(bb.w + u0 * r0.w + u1 * r1.w + u2 * r2.w + u3 * r3.w, 0.f);
        b.x = fmaxf(bb.x + w0 * r0.x + w1 * r1.x + w2 * r2.x + w3 * r3.x, 0.f);
        b.y = fmaxf(bb.y + w0 * r0.y + w1 * r1.y + w2 * r2.y + w3 * r3.y, 0.f);
        b.z = fmaxf(bb.z + w0 * r0.z + w1 * r1.z + w2 * r2.z + w3 * r3.z, 0.f);
        b.w = fmaxf(bb.w + w0 * r0.w + w1 * r1.w + w2 * r2.w + w3 * r3.w, 0.f);

        const float* wp = &sW2[k4 * 4 * 64];
#pragma unroll
        for (int c = 0; c < 64; c++) {
            float wv0 = wp[c], wv1 = wp[64 + c], wv2 = wp[128 + c], wv3 = wp[192 + c];
            acc0[c] += a.x * wv0; acc0[c] += a.y * wv1;
            acc0[c] += a.z * wv2; acc0[c] += a.w * wv3;
            acc1[c] += b.x * wv0; acc1[c] += b.y * wv1;
            acc1[c] += b.z * wv2; acc1[c] += b.w * wv3;
        }
    }
    {
        float4* o0 = &g_t2[n0 * 16];
#pragma unroll
        for (int c4 = 0; c4 < 16; c4++)
            o0[c4] = make_float4(acc0[4 * c4], acc0[4 * c4 + 1], acc0[4 * c4 + 2], acc0[4 * c4 + 3]);
    }
    if (p1) {
        float4* o1 = &g_t2[n1 * 16];
#pragma unroll
        for (int c4 = 0; c4 < 16; c4++)
            o1[c4] = make_float4(acc1[4 * c4], acc1[4 * c4 + 1], acc1[4 * c4 + 2], acc1[4 * c4 + 3]);
    }
}

// layer-2 aggregation in dim 64: 16 threads (float4 chunks) per edge
__global__ void k_agg2() {
    int idx = blockIdx.x * blockDim.x + threadIdx.x;
    if (idx >= E * 16) return;
    int e = idx >> 4, c = idx & 15;
    int s = g_src[e], d = g_dst[e];
    float nr = g_norm[e];
    float4 v = g_t2[s * 16 + c];
    v.x *= nr; v.y *= nr; v.z *= nr; v.w *= nr;
    red_add_v4((float*)&g_agg2[d * 16 + c], v);
}

// fused: h2 = relu(agg2 + dis2*t2 + b2); t3 = h2 . W3; out = dis2*t3 + b3
__global__ void k_l2gemm3(const float* __restrict__ b2, const float* __restrict__ W3,
                          const float* __restrict__ b3, float* __restrict__ out) {
    __shared__ float sw[64];
    __shared__ float sb2[64];
    if (threadIdx.x < 64) { sw[threadIdx.x] = W3[threadIdx.x]; sb2[threadIdx.x] = b2[threadIdx.x]; }
    __syncthreads();
    int gw = (blockIdx.x * blockDim.x + threadIdx.x) >> 5;
    int lane = threadIdx.x & 31;
    if (gw >= N) return;
    float s2 = 1.0f / g_deg[gw];
    float2 a = ((const float2*)((const float*)g_agg2 + gw * 64))[lane];
    float2 t = ((const float2*)((const float*)g_t2   + gw * 64))[lane];
    float h0 = fmaxf(a.x + s2 * t.x + sb2[2 * lane],     0.f);
    float h1 = fmaxf(a.y + s2 * t.y + sb2[2 * lane + 1], 0.f);
    float p = h0 * sw[2 * lane] + h1 * sw[2 * lane + 1];
#pragma unroll
    for (int off = 16; off; off >>= 1) p += __shfl_down_sync(0xffffffffu, p, off);
    if (lane == 0) {
        g_t3[gw] = p;
        out[gw] = s2 * p + b3[0];   // self-loop + bias; edge atomics add on top
    }
}

// layer-3 aggregation (scalar atomics into out)
__global__ void k_agg3(float* __restrict__ out) {
    int e = blockIdx.x * blockDim.x + threadIdx.x;
    if (e >= E) return;
    atomicAdd(&out[g_dst[e]], g_norm[e] * g_t3[g_src[e]]);
}

// ---------------- launch ----------------
extern "C" void kernel_launch(void* const* d_in, const int* in_sizes, int n_in,
                              void* d_out, int out_size) {
    const float* x  = (const float*)d_in[0];
    const int*   ei = (const int*)d_in[1];      // dtype sniffed on device
    const float* w  = (const float*)d_in[2];
    const float* W1 = (const float*)d_in[3];
    const float* b1 = (const float*)d_in[4];
    const float* W2 = (const float*)d_in[5];
    const float* b2 = (const float*)d_in[6];
    const float* W3 = (const float*)d_in[7];
    const float* b3 = (const float*)d_in[8];
    float* out = (float*)d_out;

    const int B = 256;

    k_detect_init<<<(N + B - 1) / B, B>>>(ei);
    k_decode_deg<<<(E + B - 1) / B, B>>>(ei, w);
    k_norm_agg1<<<(E + B - 1) / B, B>>>(x, w);
    k_l1gemm2<<<(N + 255) / 256, 128>>>(x, W1, b1, W2);
    k_agg2<<<(E * 16 + B - 1) / B, B>>>();
    k_l2gemm3<<<(N * 32 + B - 1) / B, B>>>(b2, W3, b3, out);
    k_agg3<<<(E + B - 1) / B, B>>>(out);
}

// round 9
// speedup vs baseline: 1.0446x; 1.0080x over previous
#include <cuda_runtime.h>
#include <cuda_bf16.h>

// GCN 3-layer, N=100000, E=800000. Aggregate in the smaller dim per layer.
// Self-loop (norm = 1/deg) folded into per-node combine steps.
// R8: k_l1gemm2 occupancy fix. R7's M=2 blocking was right (LDS floor == FMA
//     floor ~48us) but 213 regs -> occ 10.9% -> pipes serialized (76us).
//     Split the 64 output columns into two 32-column passes over k:
//     64 acc floats instead of 128 -> ~130 regs -> 2x warps -> LDS/FMA overlap.

static constexpr int N = 100000;
static constexpr int E = 800000;

__device__ float4 g_agg1[N];        // [N,4]
__device__ float4 g_t2[N * 16];     // [N,64]  (x@W1->relu)@W2
__device__ float4 g_agg2[N * 16];   // [N,64]
__device__ float  g_t3[N];
__device__ float  g_deg[N];
__device__ float  g_norm[E];
__device__ int    g_src[E];
__device__ int    g_dst[E];
__device__ int    g_is64;

__device__ __forceinline__ void red_add_v4(float* p, float4 v) {
    asm volatile("red.global.add.v4.f32 [%0], {%1,%2,%3,%4};"
                 :: "l"(p), "f"(v.x), "f"(v.y), "f"(v.z), "f"(v.w)
                 : "memory");
}

// ---------------- kernels ----------------

// grid-wide: init deg=1 (self-loop) and agg1=0; block 0 sniffs edge dtype.
__global__ void k_detect_init(const int* __restrict__ ei32) {
    int i = blockIdx.x * blockDim.x + threadIdx.x;
    int stride = gridDim.x * blockDim.x;
    const float4 z4 = make_float4(0.f, 0.f, 0.f, 0.f);
    for (int j = i; j < N; j += stride) {
        g_deg[j] = 1.0f;
        g_agg1[j] = z4;
    }
    if (blockIdx.x == 0) {
        __shared__ unsigned s[256];
        unsigned acc = 0;
        for (int t = threadIdx.x; t < 8192; t += 256) acc |= (unsigned)ei32[2 * t + 1];
        s[threadIdx.x] = acc;
        __syncthreads();
        for (int o = 128; o; o >>= 1) {
            if (threadIdx.x < o) s[threadIdx.x] |= s[threadIdx.x + o];
            __syncthreads();
        }
        if (threadIdx.x == 0) g_is64 = (s[0] == 0) ? 1 : 0;
    }
}

// decode indices (either dtype) + weighted in-degree
__global__ void k_decode_deg(const int* __restrict__ ei32, const float* __restrict__ w) {
    int e = blockIdx.x * blockDim.x + threadIdx.x;
    if (e >= E) return;
    int s, d;
    if (g_is64) { s = ei32[2 * e]; d = ei32[2 * (E + e)]; }
    else        { s = ei32[e];     d = ei32[E + e]; }
    if ((unsigned)s >= (unsigned)N) s = 0;
    if ((unsigned)d >= (unsigned)N) d = 0;
    g_src[e] = s;
    g_dst[e] = d;
    atomicAdd(&g_deg[d], w[e]);
}

// per-edge norm (rsqrt on the fly) + layer-1 aggregation (dim 4)
__global__ void k_norm_agg1(const float* __restrict__ x, const float* __restrict__ w) {
    int e = blockIdx.x * blockDim.x + threadIdx.x;
    if (e >= E) return;
    int s = g_src[e], d = g_dst[e];
    float nr = rsqrtf(g_deg[s]) * w[e] * rsqrtf(g_deg[d]);
    g_norm[e] = nr;
    float4 v = ((const float4*)x)[s];
    v.x *= nr; v.y *= nr; v.z *= nr; v.w *= nr;
    red_add_v4((float*)&g_agg1[d], v);
}

// fused l1+gemm2: 2 nodes per thread, two 32-column passes (low reg pressure).
// h1 recomputed per pass (cheap). Also zeroes the nodes' g_agg2 rows.
__global__ __launch_bounds__(128) void k_l1gemm2(
    const float* __restrict__ x, const float* __restrict__ W1,
    const float* __restrict__ b1, const float* __restrict__ W2) {
    __shared__ float sW2[128 * 64];   // 32KB
    __shared__ float sW1[4 * 128];    // 2KB
    __shared__ float sb1[128];
    for (int t = threadIdx.x; t < 128 * 64; t += 128) sW2[t] = W2[t];
    for (int t = threadIdx.x; t < 4 * 128; t += 128)  sW1[t] = W1[t];
    if (threadIdx.x < 128) sb1[threadIdx.x] = b1[threadIdx.x];
    __syncthreads();

    int n0 = blockIdx.x * 256 + threadIdx.x;   // node A
    int n1 = n0 + 128;                         // node B
    bool p1 = n1 < N;
    if (n0 >= N) return;

    const float4 z4 = make_float4(0.f, 0.f, 0.f, 0.f);
    {
        float4* a2 = &g_agg2[n0 * 16];
#pragma unroll
        for (int c = 0; c < 16; c++) a2[c] = z4;
        if (p1) {
            float4* b2z = &g_agg2[n1 * 16];
#pragma unroll
            for (int c = 0; c < 16; c++) b2z[c] = z4;
        }
    }

    float u0, u1, u2, u3;   // node A input vec
    float w0, w1, w2, w3;   // node B input vec
    {
        float4 ag = g_agg1[n0];
        float4 xv = ((const float4*)x)[n0];
        float s2 = 1.0f / g_deg[n0];
        u0 = ag.x + s2 * xv.x; u1 = ag.y + s2 * xv.y;
        u2 = ag.z + s2 * xv.z; u3 = ag.w + s2 * xv.w;
    }
    if (p1) {
        float4 ag = g_agg1[n1];
        float4 xv = ((const float4*)x)[n1];
        float s2 = 1.0f / g_deg[n1];
        w0 = ag.x + s2 * xv.x; w1 = ag.y + s2 * xv.y;
        w2 = ag.z + s2 * xv.z; w3 = ag.w + s2 * xv.w;
    } else {
        w0 = w1 = w2 = w3 = 0.f;
    }

#pragma unroll 1
    for (int pass = 0; pass < 2; pass++) {
        float acc0[32], acc1[32];
#pragma unroll
        for (int c = 0; c < 32; c++) { acc0[c] = 0.f; acc1[c] = 0.f; }

        const float* sW2p = sW2 + pass * 32;

#pragma unroll 1
        for (int k4 = 0; k4 < 32; k4++) {
            float4 r0 = ((const float4*)sW1)[k4];
            float4 r1 = ((const float4*)(sW1 + 128))[k4];
            float4 r2 = ((const float4*)(sW1 + 256))[k4];
            float4 r3 = ((const float4*)(sW1 + 384))[k4];
            float4 bb = ((const float4*)sb1)[k4];
            float4 a, b;
            a.x = fmaxf(bb.x + u0 * r0.x + u1 * r1.x + u2 * r2.x + u3 * r3.x, 0.f);
            a.y = fmaxf(bb.y + u0 * r0.y + u1 * r1.y + u2 * r2.y + u3 * r3.y, 0.f);
            a.z = fmaxf(bb.z + u0 * r0.z + u1 * r1.z + u2 * r2.z + u3 * r3.z, 0.f);
            a.w = fmaxf(bb.w + u0 * r0.w + u1 * r1.w + u2 * r2.w + u3 * r3.w, 0.f);
            b.x = fmaxf(bb.x + w0 * r0.x + w1 * r1.x + w2 * r2.x + w3 * r3.x, 0.f);
            b.y = fmaxf(bb.y + w0 * r0.y + w1 * r1.y + w2 * r2.y + w3 * r3.y, 0.f);
            b.z = fmaxf(bb.z + w0 * r0.z + w1 * r1.z + w2 * r2.z + w3 * r3.z, 0.f);
            b.w = fmaxf(bb.w + w0 * r0.w + w1 * r1.w + w2 * r2.w + w3 * r3.w, 0.f);

            const float* wp = &sW2p[k4 * 4 * 64];
#pragma unroll
            for (int c = 0; c < 32; c++) {
                float wv0 = wp[c], wv1 = wp[64 + c], wv2 = wp[128 + c], wv3 = wp[192 + c];
                acc0[c] += a.x * wv0; acc0[c] += a.y * wv1;
                acc0[c] += a.z * wv2; acc0[c] += a.w * wv3;
                acc1[c] += b.x * wv0; acc1[c] += b.y * wv1;
                acc1[c] += b.z * wv2; acc1[c] += b.w * wv3;
            }
        }

        float4* o0 = &g_t2[n0 * 16 + pass * 8];
#pragma unroll
        for (int c4 = 0; c4 < 8; c4++)
            o0[c4] = make_float4(acc0[4 * c4], acc0[4 * c4 + 1], acc0[4 * c4 + 2], acc0[4 * c4 + 3]);
        if (p1) {
            float4* o1 = &g_t2[n1 * 16 + pass * 8];
#pragma unroll
            for (int c4 = 0; c4 < 8; c4++)
                o1[c4] = make_float4(acc1[4 * c4], acc1[4 * c4 + 1], acc1[4 * c4 + 2], acc1[4 * c4 + 3]);
        }
    }
}

// layer-2 aggregation in dim 64: 16 threads (float4 chunks) per edge
__global__ void k_agg2() {
    int idx = blockIdx.x * blockDim.x + threadIdx.x;
    if (idx >= E * 16) return;
    int e = idx >> 4, c = idx & 15;
    int s = g_src[e], d = g_dst[e];
    float nr = g_norm[e];
    float4 v = g_t2[s * 16 + c];
    v.x *= nr; v.y *= nr; v.z *= nr; v.w *= nr;
    red_add_v4((float*)&g_agg2[d * 16 + c], v);
}

// fused: h2 = relu(agg2 + dis2*t2 + b2); t3 = h2 . W3; out = dis2*t3 + b3
__global__ void k_l2gemm3(const float* __restrict__ b2, const float* __restrict__ W3,
                          const float* __restrict__ b3, float* __restrict__ out) {
    __shared__ float sw[64];
    __shared__ float sb2[64];
    if (threadIdx.x < 64) { sw[threadIdx.x] = W3[threadIdx.x]; sb2[threadIdx.x] = b2[threadIdx.x]; }
    __syncthreads();
    int gw = (blockIdx.x * blockDim.x + threadIdx.x) >> 5;
    int lane = threadIdx.x & 31;
    if (gw >= N) return;
    float s2 = 1.0f / g_deg[gw];
    float2 a = ((const float2*)((const float*)g_agg2 + gw * 64))[lane];
    float2 t = ((const float2*)((const float*)g_t2   + gw * 64))[lane];
    float h0 = fmaxf(a.x + s2 * t.x + sb2[2 * lane],     0.f);
    float h1 = fmaxf(a.y + s2 * t.y + sb2[2 * lane + 1], 0.f);
    float p = h0 * sw[2 * lane] + h1 * sw[2 * lane + 1];
#pragma unroll
    for (int off = 16; off; off >>= 1) p += __shfl_down_sync(0xffffffffu, p, off);
    if (lane == 0) {
        g_t3[gw] = p;
        out[gw] = s2 * p + b3[0];   // self-loop + bias; edge atomics add on top
    }
}

// layer-3 aggregation (scalar atomics into out)
__global__ void k_agg3(float* __restrict__ out) {
    int e = blockIdx.x * blockDim.x + threadIdx.x;
    if (e >= E) return;
    atomicAdd(&out[g_dst[e]], g_norm[e] * g_t3[g_src[e]]);
}

// ---------------- launch ----------------
extern "C" void kernel_launch(void* const* d_in, const int* in_sizes, int n_in,
                              void* d_out, int out_size) {
    const float* x  = (const float*)d_in[0];
    const int*   ei = (const int*)d_in[1];      // dtype sniffed on device
    const float* w  = (const float*)d_in[2];
    const float* W1 = (const float*)d_in[3];
    const float* b1 = (const float*)d_in[4];
    const float* W2 = (const float*)d_in[5];
    const float* b2 = (const float*)d_in[6];
    const float* W3 = (const float*)d_in[7];
    const float* b3 = (const float*)d_in[8];
    float* out = (float*)d_out;

    const int B = 256;

    k_detect_init<<<(N + B - 1) / B, B>>>(ei);
    k_decode_deg<<<(E + B - 1) / B, B>>>(ei, w);
    k_norm_agg1<<<(E + B - 1) / B, B>>>(x, w);
    k_l1gemm2<<<(N + 255) / 256, 128>>>(x, W1, b1, W2);
    k_agg2<<<(E * 16 + B - 1) / B, B>>>();
    k_l2gemm3<<<(N * 32 + B - 1) / B, B>>>(b2, W3, b3, out);
    k_agg3<<<(E + B - 1) / B, B>>>(out);
}